// round 2
// baseline (speedup 1.0000x reference)
#include <cuda_runtime.h>
#include <cuda_bf16.h>
#include <cstdint>

// Shapes
#define VSZ   32000
#define ESZ   512
#define HSZ   512
#define BSZ   64
#define TSZ   65          // sequence steps
#define G3    1536        // 3*H
#define MROWS (BSZ*TSZ)   // 4160 output rows

// ---------------- device scratch (static allocations only) ----------------
__device__ float          g_HA[2 * BSZ * HSZ];
__device__ float          g_HB[2 * BSZ * HSZ];
__device__ float          g_GI0[TSZ * BSZ * G3];        // 25.6 MB
__device__ __nv_bfloat16  g_WFCb[(size_t)VSZ * HSZ];    // 32.8 MB
__device__ __nv_bfloat16  g_YSb[(size_t)MROWS * HSZ];   // 4.3 MB
__device__ float          g_SUMEXP[MROWS];
__device__ float          g_LSE[MROWS];

__device__ __forceinline__ float sigf(float x) { return 1.f / (1.f + __expf(-x)); }

// ---------------- h0 = tanh(ctx @ W_init^T + b_init); also zero SUMEXP ----
__global__ void k_h0(const float* __restrict__ ctx,
                     const float* __restrict__ W_init,
                     const float* __restrict__ b_init)
{
    // grid 128 blocks (l,b), 128 threads
    const int lb = blockIdx.x;
    const int l = lb >> 6, b = lb & 63;
    const int tid = threadIdx.x;
    __shared__ float cs[HSZ];
    ((float4*)cs)[tid] = ((const float4*)(ctx + (size_t)lb * HSZ))[tid];

    const int gid = blockIdx.x * 128 + tid;
    if (gid < MROWS) g_SUMEXP[gid] = 0.f;
    __syncthreads();

    float* hout = (l == 0) ? g_HA : g_HB;   // buffer index 0
#pragma unroll
    for (int jj = 0; jj < 4; jj++) {
        const int j = tid * 4 + jj;
        const float* wr = W_init + (size_t)j * HSZ;
        float acc = 0.f;
        for (int k = 0; k < HSZ; k += 4) {
            float4 w = *(const float4*)(wr + k);
            acc += w.x * cs[k] + w.y * cs[k+1] + w.z * cs[k+2] + w.w * cs[k+3];
        }
        hout[b * HSZ + j] = tanhf(acc + b_init[j]);
    }
}

// ---------------- W_fc fp32 -> bf16 ---------------------------------------
__global__ void k_cvt_wfc(const float* __restrict__ wfc)
{
    const size_t i = (size_t)blockIdx.x * 256 + threadIdx.x;   // 4.096M float4s
    float4 v = ((const float4*)wfc)[i];
    __nv_bfloat162 lo = __floats2bfloat162_rn(v.x, v.y);
    __nv_bfloat162 hi = __floats2bfloat162_rn(v.z, v.w);
    uint2 o; o.x = *(uint32_t*)&lo; o.y = *(uint32_t*)&hi;
    ((uint2*)g_WFCb)[i] = o;
}

// ---------------- GI0[t,b,:] = emb[tok(t,b)] @ Wi0^T + bi0 ----------------
__global__ void k_gi0(const float* __restrict__ emb,
                      const int*   __restrict__ targets,
                      const float* __restrict__ Wi0,
                      const float* __restrict__ bi0)
{
    // grid (24, 65), 256 threads; tile 64(m=b) x 64(n)
    const int bn = blockIdx.x * 64;
    const int t  = blockIdx.y;
    const int tid = threadIdx.x;
    const int tx = tid & 15, ty = tid >> 4;
    __shared__ float As[64][33];
    __shared__ float Bs[64][33];
    __shared__ int   toks[64];
    if (tid < 64) toks[tid] = (t == 0) ? 1 : targets[tid * TSZ + t - 1];
    __syncthreads();

    float acc[4][4];
#pragma unroll
    for (int i = 0; i < 4; i++)
#pragma unroll
        for (int j = 0; j < 4; j++) acc[i][j] = 0.f;

    for (int k0 = 0; k0 < ESZ; k0 += 32) {
        for (int i = tid; i < 512; i += 256) {
            int r = i >> 3, cg = (i & 7) << 2;
            float4 v = *(const float4*)(emb + (size_t)toks[r] * ESZ + k0 + cg);
            As[r][cg] = v.x; As[r][cg+1] = v.y; As[r][cg+2] = v.z; As[r][cg+3] = v.w;
        }
        for (int i = tid; i < 512; i += 256) {
            int r = i >> 3, cg = (i & 7) << 2;
            float4 v = *(const float4*)(Wi0 + (size_t)(bn + r) * ESZ + k0 + cg);
            Bs[r][cg] = v.x; Bs[r][cg+1] = v.y; Bs[r][cg+2] = v.z; Bs[r][cg+3] = v.w;
        }
        __syncthreads();
#pragma unroll
        for (int k = 0; k < 32; k++) {
            float a[4], bb[4];
#pragma unroll
            for (int i = 0; i < 4; i++) a[i] = As[ty*4+i][k];
#pragma unroll
            for (int j = 0; j < 4; j++) bb[j] = Bs[tx*4+j][k];
#pragma unroll
            for (int i = 0; i < 4; i++)
#pragma unroll
                for (int j = 0; j < 4; j++) acc[i][j] += a[i] * bb[j];
        }
        __syncthreads();
    }
#pragma unroll
    for (int i = 0; i < 4; i++) {
        const int b = ty*4 + i;
#pragma unroll
        for (int j = 0; j < 4; j++) {
            const int n = bn + tx*4 + j;
            g_GI0[((size_t)t * BSZ + b) * G3 + n] = acc[i][j] + bi0[n];
        }
    }
}

// ---------------- GRU cell 0 (hidden-side GEMM fused with gates) ----------
__global__ void k_cell0(const float* __restrict__ Wh0,
                        const float* __restrict__ bh0, int t)
{
    // grid 32 (j-chunks of 16), 128 threads
    const int c = blockIdx.x, jb = c * 16;
    const int tid = threadIdx.x;
    const int jx = tid & 7, by = tid >> 3;
    const float* __restrict__ hin  = g_HA + (t & 1) * (BSZ * HSZ);
    float*       __restrict__ hout = g_HA + ((t & 1) ^ 1) * (BSZ * HSZ);
    __shared__ float As[64][33];
    __shared__ float Bs[48][33];
    float acc[4][3][2];
#pragma unroll
    for (int i = 0; i < 4; i++)
#pragma unroll
        for (int g = 0; g < 3; g++) { acc[i][g][0] = 0.f; acc[i][g][1] = 0.f; }

    for (int k0 = 0; k0 < HSZ; k0 += 32) {
        for (int i = tid; i < 512; i += 128) {
            int r = i >> 3, cg = (i & 7) << 2;
            float4 v = *(const float4*)(hin + (size_t)r * HSZ + k0 + cg);
            As[r][cg] = v.x; As[r][cg+1] = v.y; As[r][cg+2] = v.z; As[r][cg+3] = v.w;
        }
        for (int i = tid; i < 384; i += 128) {
            int gr = i >> 3, cg = (i & 7) << 2;
            int g = gr >> 4, jj = gr & 15;
            float4 v = *(const float4*)(Wh0 + (size_t)(g * HSZ + jb + jj) * HSZ + k0 + cg);
            Bs[gr][cg] = v.x; Bs[gr][cg+1] = v.y; Bs[gr][cg+2] = v.z; Bs[gr][cg+3] = v.w;
        }
        __syncthreads();
#pragma unroll
        for (int k = 0; k < 32; k++) {
            float a0 = As[by][k], a1 = As[by+16][k], a2 = As[by+32][k], a3 = As[by+48][k];
#pragma unroll
            for (int g = 0; g < 3; g++) {
                float b0 = Bs[g*16 + jx*2][k], b1 = Bs[g*16 + jx*2 + 1][k];
                acc[0][g][0] += a0*b0; acc[0][g][1] += a0*b1;
                acc[1][g][0] += a1*b0; acc[1][g][1] += a1*b1;
                acc[2][g][0] += a2*b0; acc[2][g][1] += a2*b1;
                acc[3][g][0] += a3*b0; acc[3][g][1] += a3*b1;
            }
        }
        __syncthreads();
    }
#pragma unroll
    for (int bi = 0; bi < 4; bi++) {
        const int b = by + 16 * bi;
        const float* gib = g_GI0 + ((size_t)t * BSZ + b) * G3;
#pragma unroll
        for (int jj = 0; jj < 2; jj++) {
            const int j = jb + jx*2 + jj;
            float hr = acc[bi][0][jj] + bh0[j];
            float hz = acc[bi][1][jj] + bh0[HSZ + j];
            float hn = acc[bi][2][jj] + bh0[2*HSZ + j];
            float r = sigf(gib[j] + hr);
            float z = sigf(gib[HSZ + j] + hz);
            float n = tanhf(gib[2*HSZ + j] + r * hn);
            hout[b * HSZ + j] = (1.f - z) * n + z * hin[b * HSZ + j];
        }
    }
}

// ---------------- GRU cell 1 (input + hidden GEMMs fused with gates) ------
__global__ void k_cell1(const float* __restrict__ Wi1,
                        const float* __restrict__ Wh1,
                        const float* __restrict__ bi1,
                        const float* __restrict__ bh1, int t)
{
    const int c = blockIdx.x, jb = c * 16;
    const int tid = threadIdx.x;
    const int jx = tid & 7, by = tid >> 3;
    const float* __restrict__ hx   = g_HA + ((t & 1) ^ 1) * (BSZ * HSZ);  // hA_new
    const float* __restrict__ hin  = g_HB + (t & 1) * (BSZ * HSZ);
    float*       __restrict__ hout = g_HB + ((t & 1) ^ 1) * (BSZ * HSZ);
    __shared__ float Ax[64][33], Ah[64][33];
    __shared__ float Bi_[48][33], Bh_[48][33];
    float accx[4][3][2], acch[4][3][2];
#pragma unroll
    for (int i = 0; i < 4; i++)
#pragma unroll
        for (int g = 0; g < 3; g++) {
            accx[i][g][0]=0.f; accx[i][g][1]=0.f;
            acch[i][g][0]=0.f; acch[i][g][1]=0.f;
        }

    for (int k0 = 0; k0 < HSZ; k0 += 32) {
        for (int i = tid; i < 512; i += 128) {
            int r = i >> 3, cg = (i & 7) << 2;
            float4 v = *(const float4*)(hx + (size_t)r * HSZ + k0 + cg);
            Ax[r][cg]=v.x; Ax[r][cg+1]=v.y; Ax[r][cg+2]=v.z; Ax[r][cg+3]=v.w;
            float4 w = *(const float4*)(hin + (size_t)r * HSZ + k0 + cg);
            Ah[r][cg]=w.x; Ah[r][cg+1]=w.y; Ah[r][cg+2]=w.z; Ah[r][cg+3]=w.w;
        }
        for (int i = tid; i < 384; i += 128) {
            int gr = i >> 3, cg = (i & 7) << 2;
            int g = gr >> 4, jj = gr & 15;
            size_t roff = (size_t)(g * HSZ + jb + jj) * HSZ + k0 + cg;
            float4 v = *(const float4*)(Wi1 + roff);
            Bi_[gr][cg]=v.x; Bi_[gr][cg+1]=v.y; Bi_[gr][cg+2]=v.z; Bi_[gr][cg+3]=v.w;
            float4 w = *(const float4*)(Wh1 + roff);
            Bh_[gr][cg]=w.x; Bh_[gr][cg+1]=w.y; Bh_[gr][cg+2]=w.z; Bh_[gr][cg+3]=w.w;
        }
        __syncthreads();
#pragma unroll
        for (int k = 0; k < 32; k++) {
            float x0 = Ax[by][k], x1 = Ax[by+16][k], x2 = Ax[by+32][k], x3 = Ax[by+48][k];
            float h0 = Ah[by][k], h1 = Ah[by+16][k], h2 = Ah[by+32][k], h3 = Ah[by+48][k];
#pragma unroll
            for (int g = 0; g < 3; g++) {
                float bx0 = Bi_[g*16 + jx*2][k], bx1 = Bi_[g*16 + jx*2 + 1][k];
                float bh0v = Bh_[g*16 + jx*2][k], bh1v = Bh_[g*16 + jx*2 + 1][k];
                accx[0][g][0] += x0*bx0; accx[0][g][1] += x0*bx1;
                accx[1][g][0] += x1*bx0; accx[1][g][1] += x1*bx1;
                accx[2][g][0] += x2*bx0; accx[2][g][1] += x2*bx1;
                accx[3][g][0] += x3*bx0; accx[3][g][1] += x3*bx1;
                acch[0][g][0] += h0*bh0v; acch[0][g][1] += h0*bh1v;
                acch[1][g][0] += h1*bh0v; acch[1][g][1] += h1*bh1v;
                acch[2][g][0] += h2*bh0v; acch[2][g][1] += h2*bh1v;
                acch[3][g][0] += h3*bh0v; acch[3][g][1] += h3*bh1v;
            }
        }
        __syncthreads();
    }
#pragma unroll
    for (int bi = 0; bi < 4; bi++) {
        const int b = by + 16 * bi;
#pragma unroll
        for (int jj = 0; jj < 2; jj++) {
            const int j = jb + jx*2 + jj;
            float ir = accx[bi][0][jj] + bi1[j];
            float hr = acch[bi][0][jj] + bh1[j];
            float iz = accx[bi][1][jj] + bi1[HSZ + j];
            float hz = acch[bi][1][jj] + bh1[HSZ + j];
            float in_ = accx[bi][2][jj] + bi1[2*HSZ + j];
            float hn  = acch[bi][2][jj] + bh1[2*HSZ + j];
            float r = sigf(ir + hr);
            float z = sigf(iz + hz);
            float n = tanhf(in_ + r * hn);
            float v = (1.f - z) * n + z * hin[b * HSZ + j];
            hout[b * HSZ + j] = v;
            g_YSb[(size_t)(b * TSZ + t) * HSZ + j] = __float2bfloat16(v);
        }
    }
}

// ---------------- logits GEMM (bf16 mma) + fused sum-of-exp ---------------
__device__ __forceinline__ void mma16816(float* c, const uint32_t* a, const uint32_t* b)
{
    asm volatile(
        "mma.sync.aligned.m16n8k16.row.col.f32.bf16.bf16.f32 "
        "{%0,%1,%2,%3}, {%4,%5,%6,%7}, {%8,%9}, {%0,%1,%2,%3};\n"
        : "+f"(c[0]), "+f"(c[1]), "+f"(c[2]), "+f"(c[3])
        : "r"(a[0]), "r"(a[1]), "r"(a[2]), "r"(a[3]), "r"(b[0]), "r"(b[1]));
}

__global__ void k_logits(const float* __restrict__ b_fc, float* __restrict__ out)
{
    // grid (250, 65), 256 threads. Tile 64(m) x 128(n), K=512, BK=32.
    const int bn = blockIdx.x * 128;
    const int bm = blockIdx.y * 64;
    const int tid = threadIdx.x;
    const int wid = tid >> 5, lane = tid & 31;
    const int warp_m = wid >> 2, warp_n = wid & 3;   // 2 x 4 warps
    const int g = lane >> 2, tg = lane & 3;

    __shared__ __nv_bfloat16 As[64][40];
    __shared__ __nv_bfloat16 Bs[128][40];
    __shared__ float bsm[128];
    __shared__ float ses[64];
    if (tid < 128) bsm[tid] = b_fc[bn + tid];
    if (tid < 64)  ses[tid] = 0.f;

    float acc[2][4][4];
#pragma unroll
    for (int i = 0; i < 2; i++)
#pragma unroll
        for (int j = 0; j < 4; j++)
#pragma unroll
            for (int r = 0; r < 4; r++) acc[i][j][r] = 0.f;

    for (int k0 = 0; k0 < HSZ; k0 += 32) {
        {   // A tile: 64 x 32
            int r = tid >> 2, cg = (tid & 3) << 3;
            uint4 v = *(const uint4*)(g_YSb + (size_t)(bm + r) * HSZ + k0 + cg);
            *(uint4*)&As[r][cg] = v;
        }
        {   // B tile: 128 x 32
            int r = tid >> 1, h = tid & 1;
            const uint4* src = (const uint4*)(g_WFCb + (size_t)(bn + r) * HSZ + k0 + h*16);
            *(uint4*)&Bs[r][h*16]     = src[0];
            *(uint4*)&Bs[r][h*16 + 8] = src[1];
        }
        __syncthreads();
#pragma unroll
        for (int kk = 0; kk < 32; kk += 16) {
            uint32_t af[2][4], bfr[4][2];
#pragma unroll
            for (int im = 0; im < 2; im++) {
                int r0 = warp_m*32 + im*16;
                af[im][0] = *(const uint32_t*)&As[r0 + g    ][kk + tg*2    ];
                af[im][1] = *(const uint32_t*)&As[r0 + g + 8][kk + tg*2    ];
                af[im][2] = *(const uint32_t*)&As[r0 + g    ][kk + tg*2 + 8];
                af[im][3] = *(const uint32_t*)&As[r0 + g + 8][kk + tg*2 + 8];
            }
#pragma unroll
            for (int in_ = 0; in_ < 4; in_++) {
                int c0 = warp_n*32 + in_*8;
                bfr[in_][0] = *(const uint32_t*)&Bs[c0 + g][kk + tg*2    ];
                bfr[in_][1] = *(const uint32_t*)&Bs[c0 + g][kk + tg*2 + 8];
            }
#pragma unroll
            for (int im = 0; im < 2; im++)
#pragma unroll
                for (int in_ = 0; in_ < 4; in_++)
                    mma16816(acc[im][in_], af[im], bfr[in_]);
        }
        __syncthreads();
    }

    // epilogue: add bias, store logits (float2, sector-aligned), accumulate sum(exp)
#pragma unroll
    for (int im = 0; im < 2; im++) {
#pragma unroll
        for (int half = 0; half < 2; half++) {
            const int row_l = warp_m*32 + im*16 + g + half*8;
            const int row = bm + row_l;
            float s = 0.f;
#pragma unroll
            for (int in_ = 0; in_ < 4; in_++) {
                const int col_l = warp_n*32 + in_*8 + tg*2;
                float v0 = acc[im][in_][half*2 + 0] + bsm[col_l];
                float v1 = acc[im][in_][half*2 + 1] + bsm[col_l + 1];
                float2 st; st.x = v0; st.y = v1;
                *(float2*)(out + (size_t)row * VSZ + bn + col_l) = st;
                s += __expf(v0) + __expf(v1);
            }
            atomicAdd(&ses[row_l], s);
        }
    }
    __syncthreads();
    if (tid < 64) atomicAdd(&g_SUMEXP[bm + tid], ses[tid]);
}

// ---------------- lse + fixup ---------------------------------------------
__global__ void k_lse()
{
    const int i = blockIdx.x * 256 + threadIdx.x;
    if (i < MROWS) g_LSE[i] = logf(g_SUMEXP[i]);
}

__global__ void k_fix(float* __restrict__ out)
{
    const size_t i = (size_t)blockIdx.x * 256 + threadIdx.x;  // over float4s
    const int row = (int)(i / (VSZ / 4));
    const float l = g_LSE[row];
    float4 v = ((const float4*)out)[i];
    v.x -= l; v.y -= l; v.z -= l; v.w -= l;
    ((float4*)out)[i] = v;
}

// ---------------- launch ---------------------------------------------------
extern "C" void kernel_launch(void* const* d_in, const int* in_sizes, int n_in,
                              void* d_out, int out_size)
{
    const float* ctx     = (const float*)d_in[0];
    const int*   targets = (const int*)  d_in[1];
    const float* emb     = (const float*)d_in[2];
    const float* W_init  = (const float*)d_in[3];
    const float* b_init  = (const float*)d_in[4];
    const float* Wi0     = (const float*)d_in[5];
    const float* Wh0     = (const float*)d_in[6];
    const float* bi0     = (const float*)d_in[7];
    const float* bh0     = (const float*)d_in[8];
    const float* Wi1     = (const float*)d_in[9];
    const float* Wh1     = (const float*)d_in[10];
    const float* bi1     = (const float*)d_in[11];
    const float* bh1     = (const float*)d_in[12];
    const float* W_fc    = (const float*)d_in[13];
    const float* b_fc    = (const float*)d_in[14];
    float* out = (float*)d_out;

    k_h0<<<128, 128>>>(ctx, W_init, b_init);
    k_cvt_wfc<<<(VSZ * HSZ / 4) / 256, 256>>>(W_fc);          // 16000 blocks
    k_gi0<<<dim3(24, TSZ), 256>>>(emb, targets, Wi0, bi0);

    for (int t = 0; t < TSZ; t++) {
        k_cell0<<<32, 128>>>(Wh0, bh0, t);
        k_cell1<<<32, 128>>>(Wi1, Wh1, bi1, bh1, t);
    }

    k_logits<<<dim3(VSZ / 128, MROWS / 64), 256>>>(b_fc, out);
    k_lse<<<(MROWS + 255) / 256, 256>>>();
    k_fix<<<((size_t)MROWS * VSZ / 4) / 256, 256>>>(out);     // 130000 blocks
}

// round 3
// speedup vs baseline: 2.2795x; 2.2795x over previous
#include <cuda_runtime.h>
#include <cuda_bf16.h>
#include <cstdint>

// Shapes
#define VSZ   32000
#define ESZ   512
#define HSZ   512
#define BSZ   64
#define TSZ   65          // sequence steps
#define G3    1536        // 3*H
#define MROWS (BSZ*TSZ)   // 4160 output rows

#define NC    64          // persistent scan CTAs (1 wave, co-resident)
#define WPAD  516         // 512 + 4 pad (bank-conflict-free B frags)
#define APAD  132         // 128 + 4 pad

// ---------------- device scratch (static allocations only) ----------------
__device__ float          g_HA[2 * BSZ * HSZ];
__device__ float          g_HB[2 * BSZ * HSZ];
__device__ float          g_GI0[TSZ * BSZ * G3];        // 25.6 MB
__device__ __nv_bfloat16  g_WFCb[(size_t)VSZ * HSZ];    // 32.8 MB
__device__ __nv_bfloat16  g_YSb[(size_t)MROWS * HSZ];   // 4.3 MB
__device__ float          g_SUMEXP[MROWS];
__device__ unsigned       g_cnt;

__device__ __forceinline__ float sigf(float x) { return 1.f / (1.f + __expf(-x)); }

__device__ __forceinline__ float tf32r(float x) {
    asm("cvt.rna.tf32.f32 %0, %1;" : "=f"(x) : "f"(x));
    return x;
}

__device__ __forceinline__ void mma_tf32(float* c, const uint32_t* a, uint32_t b0, uint32_t b1) {
    asm volatile(
        "mma.sync.aligned.m16n8k8.row.col.f32.tf32.tf32.f32 "
        "{%0,%1,%2,%3}, {%4,%5,%6,%7}, {%8,%9}, {%0,%1,%2,%3};\n"
        : "+f"(c[0]), "+f"(c[1]), "+f"(c[2]), "+f"(c[3])
        : "r"(a[0]), "r"(a[1]), "r"(a[2]), "r"(a[3]), "r"(b0), "r"(b1));
}

// grid-wide barrier: monotonic counter, no reset races
__device__ __forceinline__ void gbar(unsigned target) {
    __threadfence();
    __syncthreads();
    if (threadIdx.x == 0) {
        atomicAdd(&g_cnt, 1u);
        while (atomicAdd(&g_cnt, 0u) < target) { }
        __threadfence();
    }
    __syncthreads();
}

// ---------------- h0 = tanh(ctx @ W_init^T + b_init); zero SUMEXP,cnt -----
__global__ void k_h0(const float* __restrict__ ctx,
                     const float* __restrict__ W_init,
                     const float* __restrict__ b_init)
{
    const int lb = blockIdx.x;
    const int l = lb >> 6, b = lb & 63;
    const int tid = threadIdx.x;
    __shared__ float cs[HSZ];
    ((float4*)cs)[tid] = ((const float4*)(ctx + (size_t)lb * HSZ))[tid];

    const int gid = blockIdx.x * 128 + tid;
    if (gid < MROWS) g_SUMEXP[gid] = 0.f;
    if (gid == 0) g_cnt = 0;
    __syncthreads();

    float* hout = (l == 0) ? g_HA : g_HB;   // buffer index 0
#pragma unroll
    for (int jj = 0; jj < 4; jj++) {
        const int j = tid * 4 + jj;
        const float* wr = W_init + (size_t)j * HSZ;
        float acc = 0.f;
        for (int k = 0; k < HSZ; k += 4) {
            float4 w = *(const float4*)(wr + k);
            acc += w.x * cs[k] + w.y * cs[k+1] + w.z * cs[k+2] + w.w * cs[k+3];
        }
        hout[b * HSZ + j] = tanhf(acc + b_init[j]);
    }
}

// ---------------- W_fc fp32 -> bf16 ---------------------------------------
__global__ void k_cvt_wfc(const float* __restrict__ wfc)
{
    const size_t i = (size_t)blockIdx.x * 256 + threadIdx.x;
    float4 v = ((const float4*)wfc)[i];
    __nv_bfloat162 lo = __floats2bfloat162_rn(v.x, v.y);
    __nv_bfloat162 hi = __floats2bfloat162_rn(v.z, v.w);
    uint2 o; o.x = *(uint32_t*)&lo; o.y = *(uint32_t*)&hi;
    ((uint2*)g_WFCb)[i] = o;
}

// ---------------- GI0[t,b,:] = emb[tok(t,b)] @ Wi0^T + bi0 ----------------
__global__ void k_gi0(const float* __restrict__ emb,
                      const int*   __restrict__ targets,
                      const float* __restrict__ Wi0,
                      const float* __restrict__ bi0)
{
    const int bn = blockIdx.x * 64;
    const int t  = blockIdx.y;
    const int tid = threadIdx.x;
    const int tx = tid & 15, ty = tid >> 4;
    __shared__ float As[64][33];
    __shared__ float Bs[64][33];
    __shared__ int   toks[64];
    if (tid < 64) toks[tid] = (t == 0) ? 1 : targets[tid * TSZ + t - 1];
    __syncthreads();

    float acc[4][4];
#pragma unroll
    for (int i = 0; i < 4; i++)
#pragma unroll
        for (int j = 0; j < 4; j++) acc[i][j] = 0.f;

    for (int k0 = 0; k0 < ESZ; k0 += 32) {
        for (int i = tid; i < 512; i += 256) {
            int r = i >> 3, cg = (i & 7) << 2;
            float4 v = *(const float4*)(emb + (size_t)toks[r] * ESZ + k0 + cg);
            As[r][cg] = v.x; As[r][cg+1] = v.y; As[r][cg+2] = v.z; As[r][cg+3] = v.w;
        }
        for (int i = tid; i < 512; i += 256) {
            int r = i >> 3, cg = (i & 7) << 2;
            float4 v = *(const float4*)(Wi0 + (size_t)(bn + r) * ESZ + k0 + cg);
            Bs[r][cg] = v.x; Bs[r][cg+1] = v.y; Bs[r][cg+2] = v.z; Bs[r][cg+3] = v.w;
        }
        __syncthreads();
#pragma unroll
        for (int k = 0; k < 32; k++) {
            float a[4], bb[4];
#pragma unroll
            for (int i = 0; i < 4; i++) a[i] = As[ty*4+i][k];
#pragma unroll
            for (int j = 0; j < 4; j++) bb[j] = Bs[tx*4+j][k];
#pragma unroll
            for (int i = 0; i < 4; i++)
#pragma unroll
                for (int j = 0; j < 4; j++) acc[i][j] += a[i] * bb[j];
        }
        __syncthreads();
    }
#pragma unroll
    for (int i = 0; i < 4; i++) {
        const int b = ty*4 + i;
#pragma unroll
        for (int j = 0; j < 4; j++) {
            const int n = bn + tx*4 + j;
            g_GI0[((size_t)t * BSZ + b) * G3 + n] = acc[i][j] + bi0[n];
        }
    }
}

// ---------------- persistent fused GRU scan (both cells, all 65 steps) ----
// 64 CTAs x 128 threads. CTA c owns j in [8c, 8c+8) for all 3 gates.
// Weights tf32-resident in SMEM; GEMMs via mma.m16n8k8.tf32.
__global__ void __launch_bounds__(128, 1) k_scan(
    const float* __restrict__ Wh0, const float* __restrict__ bh0,
    const float* __restrict__ Wi1, const float* __restrict__ Wh1,
    const float* __restrict__ bi1, const float* __restrict__ bh1)
{
    extern __shared__ float sm[];
    float* Wh0s = sm;                    // [24][WPAD]
    float* Wi1s = sm + 24 * WPAD;
    float* Wh1s = sm + 48 * WPAD;
    float* Axs  = sm + 72 * WPAD;        // [64][APAD]
    float* Ahs  = Axs + 64 * APAD;

    const int tid  = threadIdx.x;
    const int wid  = tid >> 5, lane = tid & 31;
    const int g    = lane >> 2, tg = lane & 3;
    const int m0   = wid * 16;
    const int jb   = blockIdx.x * 8;

    // ---- load weight slices once (tf32-truncated) ----
    for (int r = 0; r < 24; r++) {
        const int gate = r >> 3, jj = r & 7;
        const size_t grow = (size_t)(gate * HSZ + jb + jj) * HSZ + tid * 4;
        float4 v0 = *(const float4*)(Wh0 + grow);
        float4 v1 = *(const float4*)(Wi1 + grow);
        float4 v2 = *(const float4*)(Wh1 + grow);
        const int o = r * WPAD + tid * 4;
        Wh0s[o+0]=tf32r(v0.x); Wh0s[o+1]=tf32r(v0.y); Wh0s[o+2]=tf32r(v0.z); Wh0s[o+3]=tf32r(v0.w);
        Wi1s[o+0]=tf32r(v1.x); Wi1s[o+1]=tf32r(v1.y); Wi1s[o+2]=tf32r(v1.z); Wi1s[o+3]=tf32r(v1.w);
        Wh1s[o+0]=tf32r(v2.x); Wh1s[o+1]=tf32r(v2.y); Wh1s[o+2]=tf32r(v2.z); Wh1s[o+3]=tf32r(v2.w);
    }
    __syncthreads();

    // ---- preload biases for this thread's 2 j columns ----
    float bg0[3][2], bgi1[3][2], bgh1[3][2];
#pragma unroll
    for (int gi = 0; gi < 3; gi++)
#pragma unroll
        for (int cc = 0; cc < 2; cc++) {
            const int j = gi * HSZ + jb + 2 * tg + cc;
            bg0[gi][cc]  = bh0[j];
            bgi1[gi][cc] = bi1[j];
            bgh1[gi][cc] = bh1[j];
        }

    unsigned nbar = 0;
    for (int t = 0; t < TSZ; t++) {
        const float* hAin  = g_HA + (t & 1) * (BSZ * HSZ);
        float*       hAout = g_HA + ((t & 1) ^ 1) * (BSZ * HSZ);
        const float* hBin  = g_HB + (t & 1) * (BSZ * HSZ);
        float*       hBout = g_HB + ((t & 1) ^ 1) * (BSZ * HSZ);

        // ======== cell0: gh = hAin @ Wh0^T (slice) ========
        float acc0[3][4];
#pragma unroll
        for (int gi = 0; gi < 3; gi++)
#pragma unroll
            for (int r = 0; r < 4; r++) acc0[gi][r] = 0.f;

        for (int kc = 0; kc < HSZ; kc += 128) {
            {   // stage A chunk: 64 x 128, L1-bypass loads
                const int r = tid >> 1, hf = tid & 1;
                const float4* src = (const float4*)(hAin + (size_t)r * HSZ + kc + hf * 64);
                float* dst = Axs + r * APAD + hf * 64;
#pragma unroll
                for (int i = 0; i < 16; i++) {
                    float4 v = __ldcg(src + i);
                    dst[i*4+0]=tf32r(v.x); dst[i*4+1]=tf32r(v.y);
                    dst[i*4+2]=tf32r(v.z); dst[i*4+3]=tf32r(v.w);
                }
            }
            __syncthreads();
#pragma unroll
            for (int kk = 0; kk < 128; kk += 8) {
                uint32_t a[4];
                const float* ar = Axs + (m0 + g) * APAD + kk + tg;
                a[0] = __float_as_uint(ar[0]);
                a[1] = __float_as_uint(ar[8 * APAD]);
                a[2] = __float_as_uint(ar[4]);
                a[3] = __float_as_uint(ar[8 * APAD + 4]);
#pragma unroll
                for (int gi = 0; gi < 3; gi++) {
                    const float* br = Wh0s + (gi * 8 + g) * WPAD + kc + kk + tg;
                    mma_tf32(acc0[gi], a, __float_as_uint(br[0]), __float_as_uint(br[4]));
                }
            }
            __syncthreads();
        }
        // epilogue cell0
#pragma unroll
        for (int hf = 0; hf < 2; hf++) {
            const int b = m0 + g + 8 * hf;
            const float* gi0p = g_GI0 + ((size_t)t * BSZ + b) * G3;
#pragma unroll
            for (int cc = 0; cc < 2; cc++) {
                const int j = jb + 2 * tg + cc;
                const float r = sigf(__ldg(gi0p + j)           + acc0[0][hf*2+cc] + bg0[0][cc]);
                const float z = sigf(__ldg(gi0p + HSZ + j)     + acc0[1][hf*2+cc] + bg0[1][cc]);
                const float n = tanhf(__ldg(gi0p + 2*HSZ + j)  + r * (acc0[2][hf*2+cc] + bg0[2][cc]));
                const float hprev = __ldcg(hAin + (size_t)b * HSZ + j);
                hAout[(size_t)b * HSZ + j] = (1.f - z) * n + z * hprev;
            }
        }
        gbar(++nbar * NC);

        // ======== cell1: gi = hAout @ Wi1^T, gh = hBin @ Wh1^T ========
        float accx[3][4], acch[3][4];
#pragma unroll
        for (int gi = 0; gi < 3; gi++)
#pragma unroll
            for (int r = 0; r < 4; r++) { accx[gi][r] = 0.f; acch[gi][r] = 0.f; }

        for (int kc = 0; kc < HSZ; kc += 128) {
            {
                const int r = tid >> 1, hf = tid & 1;
                const float4* sx = (const float4*)(hAout + (size_t)r * HSZ + kc + hf * 64);
                const float4* sh = (const float4*)(hBin  + (size_t)r * HSZ + kc + hf * 64);
                float* dx = Axs + r * APAD + hf * 64;
                float* dh = Ahs + r * APAD + hf * 64;
#pragma unroll
                for (int i = 0; i < 16; i++) {
                    float4 v = __ldcg(sx + i);
                    dx[i*4+0]=tf32r(v.x); dx[i*4+1]=tf32r(v.y);
                    dx[i*4+2]=tf32r(v.z); dx[i*4+3]=tf32r(v.w);
                    float4 w = __ldcg(sh + i);
                    dh[i*4+0]=tf32r(w.x); dh[i*4+1]=tf32r(w.y);
                    dh[i*4+2]=tf32r(w.z); dh[i*4+3]=tf32r(w.w);
                }
            }
            __syncthreads();
#pragma unroll
            for (int kk = 0; kk < 128; kk += 8) {
                uint32_t ax[4], ah[4];
                const float* arx = Axs + (m0 + g) * APAD + kk + tg;
                const float* arh = Ahs + (m0 + g) * APAD + kk + tg;
                ax[0]=__float_as_uint(arx[0]);        ah[0]=__float_as_uint(arh[0]);
                ax[1]=__float_as_uint(arx[8*APAD]);   ah[1]=__float_as_uint(arh[8*APAD]);
                ax[2]=__float_as_uint(arx[4]);        ah[2]=__float_as_uint(arh[4]);
                ax[3]=__float_as_uint(arx[8*APAD+4]); ah[3]=__float_as_uint(arh[8*APAD+4]);
#pragma unroll
                for (int gi = 0; gi < 3; gi++) {
                    const float* bi_ = Wi1s + (gi * 8 + g) * WPAD + kc + kk + tg;
                    const float* bh_ = Wh1s + (gi * 8 + g) * WPAD + kc + kk + tg;
                    mma_tf32(accx[gi], ax, __float_as_uint(bi_[0]), __float_as_uint(bi_[4]));
                    mma_tf32(acch[gi], ah, __float_as_uint(bh_[0]), __float_as_uint(bh_[4]));
                }
            }
            __syncthreads();
        }
        // epilogue cell1
#pragma unroll
        for (int hf = 0; hf < 2; hf++) {
            const int b = m0 + g + 8 * hf;
#pragma unroll
            for (int cc = 0; cc < 2; cc++) {
                const int j = jb + 2 * tg + cc;
                const float r = sigf(accx[0][hf*2+cc] + bgi1[0][cc] + acch[0][hf*2+cc] + bgh1[0][cc]);
                const float z = sigf(accx[1][hf*2+cc] + bgi1[1][cc] + acch[1][hf*2+cc] + bgh1[1][cc]);
                const float n = tanhf(accx[2][hf*2+cc] + bgi1[2][cc]
                                      + r * (acch[2][hf*2+cc] + bgh1[2][cc]));
                const float hprev = __ldcg(hBin + (size_t)b * HSZ + j);
                const float v = (1.f - z) * n + z * hprev;
                hBout[(size_t)b * HSZ + j] = v;
                g_YSb[((size_t)b * TSZ + t) * HSZ + j] = __float2bfloat16(v);
            }
        }
        gbar(++nbar * NC);
    }
}

// ---------------- logits GEMM (bf16 mma) + fused sum-of-exp ---------------
__device__ __forceinline__ void mma16816(float* c, const uint32_t* a, const uint32_t* b)
{
    asm volatile(
        "mma.sync.aligned.m16n8k16.row.col.f32.bf16.bf16.f32 "
        "{%0,%1,%2,%3}, {%4,%5,%6,%7}, {%8,%9}, {%0,%1,%2,%3};\n"
        : "+f"(c[0]), "+f"(c[1]), "+f"(c[2]), "+f"(c[3])
        : "r"(a[0]), "r"(a[1]), "r"(a[2]), "r"(a[3]), "r"(b[0]), "r"(b[1]));
}

__global__ void k_logits(const float* __restrict__ b_fc, float* __restrict__ out)
{
    const int bn = blockIdx.x * 128;
    const int bm = blockIdx.y * 64;
    const int tid = threadIdx.x;
    const int wid = tid >> 5, lane = tid & 31;
    const int warp_m = wid >> 2, warp_n = wid & 3;
    const int g = lane >> 2, tg = lane & 3;

    __shared__ __nv_bfloat16 As[64][40];
    __shared__ __nv_bfloat16 Bs[128][40];
    __shared__ float bsm[128];
    __shared__ float ses[64];
    if (tid < 128) bsm[tid] = b_fc[bn + tid];
    if (tid < 64)  ses[tid] = 0.f;

    float acc[2][4][4];
#pragma unroll
    for (int i = 0; i < 2; i++)
#pragma unroll
        for (int j = 0; j < 4; j++)
#pragma unroll
            for (int r = 0; r < 4; r++) acc[i][j][r] = 0.f;

    for (int k0 = 0; k0 < HSZ; k0 += 32) {
        {
            int r = tid >> 2, cg = (tid & 3) << 3;
            uint4 v = *(const uint4*)(g_YSb + (size_t)(bm + r) * HSZ + k0 + cg);
            *(uint4*)&As[r][cg] = v;
        }
        {
            int r = tid >> 1, h = tid & 1;
            const uint4* src = (const uint4*)(g_WFCb + (size_t)(bn + r) * HSZ + k0 + h*16);
            *(uint4*)&Bs[r][h*16]     = src[0];
            *(uint4*)&Bs[r][h*16 + 8] = src[1];
        }
        __syncthreads();
#pragma unroll
        for (int kk = 0; kk < 32; kk += 16) {
            uint32_t af[2][4], bfr[4][2];
#pragma unroll
            for (int im = 0; im < 2; im++) {
                int r0 = warp_m*32 + im*16;
                af[im][0] = *(const uint32_t*)&As[r0 + g    ][kk + tg*2    ];
                af[im][1] = *(const uint32_t*)&As[r0 + g + 8][kk + tg*2    ];
                af[im][2] = *(const uint32_t*)&As[r0 + g    ][kk + tg*2 + 8];
                af[im][3] = *(const uint32_t*)&As[r0 + g + 8][kk + tg*2 + 8];
            }
#pragma unroll
            for (int in_ = 0; in_ < 4; in_++) {
                int c0 = warp_n*32 + in_*8;
                bfr[in_][0] = *(const uint32_t*)&Bs[c0 + g][kk + tg*2    ];
                bfr[in_][1] = *(const uint32_t*)&Bs[c0 + g][kk + tg*2 + 8];
            }
#pragma unroll
            for (int im = 0; im < 2; im++)
#pragma unroll
                for (int in_ = 0; in_ < 4; in_++)
                    mma16816(acc[im][in_], af[im], bfr[in_]);
        }
        __syncthreads();
    }

#pragma unroll
    for (int im = 0; im < 2; im++) {
#pragma unroll
        for (int half = 0; half < 2; half++) {
            const int row_l = warp_m*32 + im*16 + g + half*8;
            const int row = bm + row_l;
            float s = 0.f;
#pragma unroll
            for (int in_ = 0; in_ < 4; in_++) {
                const int col_l = warp_n*32 + in_*8 + tg*2;
                float v0 = acc[im][in_][half*2 + 0] + bsm[col_l];
                float v1 = acc[im][in_][half*2 + 1] + bsm[col_l + 1];
                float2 st; st.x = v0; st.y = v1;
                *(float2*)(out + (size_t)row * VSZ + bn + col_l) = st;
                s += __expf(v0) + __expf(v1);
            }
            atomicAdd(&ses[row_l], s);
        }
    }
    __syncthreads();
    if (tid < 64) atomicAdd(&g_SUMEXP[bm + tid], ses[tid]);
}

// ---------------- fixup: out -= log(sumexp(row)) ---------------------------
__global__ void k_fix(float* __restrict__ out)
{
    const size_t i = (size_t)blockIdx.x * 256 + threadIdx.x;  // over float4s
    const int row = (int)(i / (VSZ / 4));
    const float l = logf(g_SUMEXP[row]);
    float4 v = ((const float4*)out)[i];
    v.x -= l; v.y -= l; v.z -= l; v.w -= l;
    ((float4*)out)[i] = v;
}

// ---------------- launch ---------------------------------------------------
extern "C" void kernel_launch(void* const* d_in, const int* in_sizes, int n_in,
                              void* d_out, int out_size)
{
    const float* ctx     = (const float*)d_in[0];
    const int*   targets = (const int*)  d_in[1];
    const float* emb     = (const float*)d_in[2];
    const float* W_init  = (const float*)d_in[3];
    const float* b_init  = (const float*)d_in[4];
    const float* Wi0     = (const float*)d_in[5];
    const float* Wh0     = (const float*)d_in[6];
    const float* bi0     = (const float*)d_in[7];
    const float* bh0     = (const float*)d_in[8];
    const float* Wi1     = (const float*)d_in[9];
    const float* Wh1     = (const float*)d_in[10];
    const float* bi1     = (const float*)d_in[11];
    const float* bh1     = (const float*)d_in[12];
    const float* W_fc    = (const float*)d_in[13];
    const float* b_fc    = (const float*)d_in[14];
    float* out = (float*)d_out;

    static int smem_set = 0;
    const int scan_smem = (72 * WPAD + 2 * 64 * APAD) * 4;   // 216192 B
    if (!smem_set) {
        cudaFuncSetAttribute(k_scan, cudaFuncAttributeMaxDynamicSharedMemorySize, scan_smem);
        smem_set = 1;
    }

    k_h0<<<128, 128>>>(ctx, W_init, b_init);
    k_cvt_wfc<<<(VSZ * HSZ / 4) / 256, 256>>>(W_fc);
    k_gi0<<<dim3(24, TSZ), 256>>>(emb, targets, Wi0, bi0);

    k_scan<<<NC, 128, scan_smem>>>(Wh0, bh0, Wi1, Wh1, bi1, bh1);

    k_logits<<<dim3(VSZ / 128, MROWS / 64), 256>>>(b_fc, out);
    k_fix<<<((size_t)MROWS * VSZ / 4) / 256, 256>>>(out);
}

// round 4
// speedup vs baseline: 3.4253x; 1.5027x over previous
#include <cuda_runtime.h>
#include <cuda_bf16.h>
#include <cstdint>

// Shapes
#define VSZ   32000
#define ESZ   512
#define HSZ   512
#define BSZ   64
#define TSZ   65          // sequence steps
#define G3    1536        // 3*H
#define MROWS (BSZ*TSZ)   // 4160 output rows

#define NC    64          // persistent scan CTAs (1 wave, co-resident)
#define WPAD  516         // 512 + 4 pad
#define APAD  132         // 128 + 4 pad

// ---------------- device scratch (static allocations only) ----------------
__device__ float          g_HA[2 * BSZ * HSZ];
__device__ float          g_HB[2 * BSZ * HSZ];
__device__ float          g_GI0[TSZ * BSZ * G3];        // 25.6 MB
__device__ __nv_bfloat16  g_WFCb[(size_t)VSZ * HSZ];    // 32.8 MB
__device__ __nv_bfloat16  g_YSb[(size_t)MROWS * HSZ];   // 4.3 MB
__device__ float          g_SUMEXP[MROWS];
__device__ unsigned       g_cnt;

__device__ __forceinline__ float sigf(float x) { return 1.f / (1.f + __expf(-x)); }

__device__ __forceinline__ float tf32r(float x) {
    asm("cvt.rna.tf32.f32 %0, %1;" : "=f"(x) : "f"(x));
    return x;
}

__device__ __forceinline__ void mma_tf32(float* c, const uint32_t* a, uint32_t b0, uint32_t b1) {
    asm volatile(
        "mma.sync.aligned.m16n8k8.row.col.f32.tf32.tf32.f32 "
        "{%0,%1,%2,%3}, {%4,%5,%6,%7}, {%8,%9}, {%0,%1,%2,%3};\n"
        : "+f"(c[0]), "+f"(c[1]), "+f"(c[2]), "+f"(c[3])
        : "r"(a[0]), "r"(a[1]), "r"(a[2]), "r"(a[3]), "r"(b0), "r"(b1));
}

// grid-wide barrier: RED arrive + LOAD-based (non-RMW) polling
__device__ __forceinline__ void gbar(unsigned target) {
    __syncthreads();
    if (threadIdx.x == 0) {
        unsigned* p = &g_cnt;
        asm volatile("red.release.gpu.global.add.u32 [%0], 1;" :: "l"(p) : "memory");
        unsigned v;
        do {
            asm volatile("ld.acquire.gpu.global.u32 %0, [%1];" : "=r"(v) : "l"(p) : "memory");
        } while (v < target);
    }
    __syncthreads();
}

// ---------------- h0 = tanh(ctx @ W_init^T + b_init); zero SUMEXP,cnt -----
__global__ void k_h0(const float* __restrict__ ctx,
                     const float* __restrict__ W_init,
                     const float* __restrict__ b_init)
{
    const int lb = blockIdx.x;
    const int l = lb >> 6, b = lb & 63;
    const int tid = threadIdx.x;
    __shared__ float cs[HSZ];
    ((float4*)cs)[tid] = ((const float4*)(ctx + (size_t)lb * HSZ))[tid];

    const int gid = blockIdx.x * 128 + tid;
    if (gid < MROWS) g_SUMEXP[gid] = 0.f;
    if (gid == 0) g_cnt = 0;
    __syncthreads();

    float* hout = (l == 0) ? g_HA : g_HB;   // buffer index 0
#pragma unroll
    for (int jj = 0; jj < 4; jj++) {
        const int j = tid * 4 + jj;
        const float* wr = W_init + (size_t)j * HSZ;
        float acc = 0.f;
        for (int k = 0; k < HSZ; k += 4) {
            float4 w = *(const float4*)(wr + k);
            acc += w.x * cs[k] + w.y * cs[k+1] + w.z * cs[k+2] + w.w * cs[k+3];
        }
        hout[b * HSZ + j] = tanhf(acc + b_init[j]);
    }
}

// ---------------- W_fc fp32 -> bf16 ---------------------------------------
__global__ void k_cvt_wfc(const float* __restrict__ wfc)
{
    const size_t i = (size_t)blockIdx.x * 256 + threadIdx.x;
    float4 v = ((const float4*)wfc)[i];
    __nv_bfloat162 lo = __floats2bfloat162_rn(v.x, v.y);
    __nv_bfloat162 hi = __floats2bfloat162_rn(v.z, v.w);
    uint2 o; o.x = *(uint32_t*)&lo; o.y = *(uint32_t*)&hi;
    ((uint2*)g_WFCb)[i] = o;
}

// ---------------- GI0[t,b,:] = emb[tok(t,b)] @ Wi0^T + bi0 ----------------
__global__ void k_gi0(const float* __restrict__ emb,
                      const int*   __restrict__ targets,
                      const float* __restrict__ Wi0,
                      const float* __restrict__ bi0)
{
    const int bn = blockIdx.x * 64;
    const int t  = blockIdx.y;
    const int tid = threadIdx.x;
    const int tx = tid & 15, ty = tid >> 4;
    __shared__ float As[64][33];
    __shared__ float Bs[64][33];
    __shared__ int   toks[64];
    if (tid < 64) toks[tid] = (t == 0) ? 1 : targets[tid * TSZ + t - 1];
    __syncthreads();

    float acc[4][4];
#pragma unroll
    for (int i = 0; i < 4; i++)
#pragma unroll
        for (int j = 0; j < 4; j++) acc[i][j] = 0.f;

    for (int k0 = 0; k0 < ESZ; k0 += 32) {
        for (int i = tid; i < 512; i += 256) {
            int r = i >> 3, cg = (i & 7) << 2;
            float4 v = *(const float4*)(emb + (size_t)toks[r] * ESZ + k0 + cg);
            As[r][cg] = v.x; As[r][cg+1] = v.y; As[r][cg+2] = v.z; As[r][cg+3] = v.w;
        }
        for (int i = tid; i < 512; i += 256) {
            int r = i >> 3, cg = (i & 7) << 2;
            float4 v = *(const float4*)(Wi0 + (size_t)(bn + r) * ESZ + k0 + cg);
            Bs[r][cg] = v.x; Bs[r][cg+1] = v.y; Bs[r][cg+2] = v.z; Bs[r][cg+3] = v.w;
        }
        __syncthreads();
#pragma unroll
        for (int k = 0; k < 32; k++) {
            float a[4], bb[4];
#pragma unroll
            for (int i = 0; i < 4; i++) a[i] = As[ty*4+i][k];
#pragma unroll
            for (int j = 0; j < 4; j++) bb[j] = Bs[tx*4+j][k];
#pragma unroll
            for (int i = 0; i < 4; i++)
#pragma unroll
                for (int j = 0; j < 4; j++) acc[i][j] += a[i] * bb[j];
        }
        __syncthreads();
    }
#pragma unroll
    for (int i = 0; i < 4; i++) {
        const int b = ty*4 + i;
#pragma unroll
        for (int j = 0; j < 4; j++) {
            const int n = bn + tx*4 + j;
            g_GI0[((size_t)t * BSZ + b) * G3 + n] = acc[i][j] + bi0[n];
        }
    }
}

// coalesced staging: each warp stages nrows contiguous rows; lane = float4 in row
template<int NR>
__device__ __forceinline__ void stage_rows(const float* __restrict__ src, float* __restrict__ dst,
                                           int kc, int lane, int row0) {
#pragma unroll
    for (int i = 0; i < NR; i++) {
        const int row = row0 + i;
        float4 v = __ldcg((const float4*)(src + (size_t)row * HSZ + kc) + lane);
        float4 w; w.x = tf32r(v.x); w.y = tf32r(v.y); w.z = tf32r(v.z); w.w = tf32r(v.w);
        *(float4*)(dst + row * APAD + lane * 4) = w;
    }
}

// ---------------- persistent fused GRU scan (both cells, all 65 steps) ----
__global__ void __launch_bounds__(128, 1) k_scan(
    const float* __restrict__ Wh0, const float* __restrict__ bh0,
    const float* __restrict__ Wi1, const float* __restrict__ Wh1,
    const float* __restrict__ bi1, const float* __restrict__ bh1)
{
    extern __shared__ float sm[];
    float* Wh0s = sm;                    // [24][WPAD]
    float* Wi1s = sm + 24 * WPAD;
    float* Wh1s = sm + 48 * WPAD;
    float* Axs  = sm + 72 * WPAD;        // [64][APAD]
    float* Ahs  = Axs + 64 * APAD;

    const int tid  = threadIdx.x;
    const int wid  = tid >> 5, lane = tid & 31;
    const int g    = lane >> 2, tg = lane & 3;
    const int m0   = wid * 16;
    const int jb   = blockIdx.x * 8;

    // ---- load weight slices once (tf32-truncated) ----
    for (int r = 0; r < 24; r++) {
        const int gate = r >> 3, jj = r & 7;
        const size_t grow = (size_t)(gate * HSZ + jb + jj) * HSZ + tid * 4;
        float4 v0 = *(const float4*)(Wh0 + grow);
        float4 v1 = *(const float4*)(Wi1 + grow);
        float4 v2 = *(const float4*)(Wh1 + grow);
        const int o = r * WPAD + tid * 4;
        Wh0s[o+0]=tf32r(v0.x); Wh0s[o+1]=tf32r(v0.y); Wh0s[o+2]=tf32r(v0.z); Wh0s[o+3]=tf32r(v0.w);
        Wi1s[o+0]=tf32r(v1.x); Wi1s[o+1]=tf32r(v1.y); Wi1s[o+2]=tf32r(v1.z); Wi1s[o+3]=tf32r(v1.w);
        Wh1s[o+0]=tf32r(v2.x); Wh1s[o+1]=tf32r(v2.y); Wh1s[o+2]=tf32r(v2.z); Wh1s[o+3]=tf32r(v2.w);
    }
    __syncthreads();

    // ---- preload biases for this thread's 2 j columns ----
    float bg0[3][2], bgi1[3][2], bgh1[3][2];
#pragma unroll
    for (int gi = 0; gi < 3; gi++)
#pragma unroll
        for (int cc = 0; cc < 2; cc++) {
            const int j = gi * HSZ + jb + 2 * tg + cc;
            bg0[gi][cc]  = bh0[j];
            bgi1[gi][cc] = bi1[j];
            bgh1[gi][cc] = bh1[j];
        }

    // ================= cell0 body (as a lambda over t) =================
    auto do_cell0 = [&](int t) {
        const float* hAin  = g_HA + (t & 1) * (BSZ * HSZ);
        float*       hAout = g_HA + ((t & 1) ^ 1) * (BSZ * HSZ);

        float acc0[3][4];
#pragma unroll
        for (int gi = 0; gi < 3; gi++)
#pragma unroll
            for (int r = 0; r < 4; r++) acc0[gi][r] = 0.f;

        for (int kc = 0; kc < HSZ; kc += 128) {
            stage_rows<16>(hAin, Axs, kc, lane, wid * 16);
            __syncthreads();
#pragma unroll
            for (int kk = 0; kk < 128; kk += 8) {
                uint32_t a[4];
                const float* ar = Axs + (m0 + g) * APAD + kk + tg;
                a[0] = __float_as_uint(ar[0]);
                a[1] = __float_as_uint(ar[8 * APAD]);
                a[2] = __float_as_uint(ar[4]);
                a[3] = __float_as_uint(ar[8 * APAD + 4]);
#pragma unroll
                for (int gi = 0; gi < 3; gi++) {
                    const float* br = Wh0s + (gi * 8 + g) * WPAD + kc + kk + tg;
                    mma_tf32(acc0[gi], a, __float_as_uint(br[0]), __float_as_uint(br[4]));
                }
            }
            __syncthreads();
        }
#pragma unroll
        for (int hf = 0; hf < 2; hf++) {
            const int b = m0 + g + 8 * hf;
            const float* gi0p = g_GI0 + ((size_t)t * BSZ + b) * G3;
#pragma unroll
            for (int cc = 0; cc < 2; cc++) {
                const int j = jb + 2 * tg + cc;
                const float r = sigf(__ldg(gi0p + j)          + acc0[0][hf*2+cc] + bg0[0][cc]);
                const float z = sigf(__ldg(gi0p + HSZ + j)    + acc0[1][hf*2+cc] + bg0[1][cc]);
                const float n = tanhf(__ldg(gi0p + 2*HSZ + j) + r * (acc0[2][hf*2+cc] + bg0[2][cc]));
                const float hprev = __ldcg(hAin + (size_t)b * HSZ + j);
                hAout[(size_t)b * HSZ + j] = (1.f - z) * n + z * hprev;
            }
        }
    };

    // ================= cell1 body =================
    auto do_cell1 = [&](int t) {
        const float* hx   = g_HA + ((t & 1) ^ 1) * (BSZ * HSZ);  // hAout(t)
        const float* hBin = g_HB + (t & 1) * (BSZ * HSZ);
        float*      hBout = g_HB + ((t & 1) ^ 1) * (BSZ * HSZ);

        float accx[3][4], acch[3][4];
#pragma unroll
        for (int gi = 0; gi < 3; gi++)
#pragma unroll
            for (int r = 0; r < 4; r++) { accx[gi][r] = 0.f; acch[gi][r] = 0.f; }

        for (int kc = 0; kc < HSZ; kc += 128) {
            if (wid < 2) stage_rows<32>(hx,   Axs, kc, lane, wid * 32);
            else         stage_rows<32>(hBin, Ahs, kc, lane, (wid - 2) * 32);
            __syncthreads();
#pragma unroll
            for (int kk = 0; kk < 128; kk += 8) {
                uint32_t ax[4], ah[4];
                const float* arx = Axs + (m0 + g) * APAD + kk + tg;
                const float* arh = Ahs + (m0 + g) * APAD + kk + tg;
                ax[0]=__float_as_uint(arx[0]);        ah[0]=__float_as_uint(arh[0]);
                ax[1]=__float_as_uint(arx[8*APAD]);   ah[1]=__float_as_uint(arh[8*APAD]);
                ax[2]=__float_as_uint(arx[4]);        ah[2]=__float_as_uint(arh[4]);
                ax[3]=__float_as_uint(arx[8*APAD+4]); ah[3]=__float_as_uint(arh[8*APAD+4]);
#pragma unroll
                for (int gi = 0; gi < 3; gi++) {
                    const float* bi_ = Wi1s + (gi * 8 + g) * WPAD + kc + kk + tg;
                    const float* bh_ = Wh1s + (gi * 8 + g) * WPAD + kc + kk + tg;
                    mma_tf32(accx[gi], ax, __float_as_uint(bi_[0]), __float_as_uint(bi_[4]));
                    mma_tf32(acch[gi], ah, __float_as_uint(bh_[0]), __float_as_uint(bh_[4]));
                }
            }
            __syncthreads();
        }
#pragma unroll
        for (int hf = 0; hf < 2; hf++) {
            const int b = m0 + g + 8 * hf;
#pragma unroll
            for (int cc = 0; cc < 2; cc++) {
                const int j = jb + 2 * tg + cc;
                const float r = sigf(accx[0][hf*2+cc] + bgi1[0][cc] + acch[0][hf*2+cc] + bgh1[0][cc]);
                const float z = sigf(accx[1][hf*2+cc] + bgi1[1][cc] + acch[1][hf*2+cc] + bgh1[1][cc]);
                const float n = tanhf(accx[2][hf*2+cc] + bgi1[2][cc]
                                      + r * (acch[2][hf*2+cc] + bgh1[2][cc]));
                const float hprev = __ldcg(hBin + (size_t)b * HSZ + j);
                const float v = (1.f - z) * n + z * hprev;
                hBout[(size_t)b * HSZ + j] = v;
                g_YSb[((size_t)b * TSZ + t) * HSZ + j] = __float2bfloat16(v);
            }
        }
    };

    // ===== phase-grouped schedule: ONE barrier per step =====
    do_cell0(0);
    gbar(NC);
    for (int t = 0; t < TSZ; t++) {
        do_cell1(t);
        if (t < TSZ - 1) {
            do_cell0(t + 1);
            gbar((unsigned)(t + 2) * NC);
        }
    }
}

// ---------------- logits GEMM (bf16 mma) + fused sum-of-exp ---------------
__device__ __forceinline__ void mma16816(float* c, const uint32_t* a, const uint32_t* b)
{
    asm volatile(
        "mma.sync.aligned.m16n8k16.row.col.f32.bf16.bf16.f32 "
        "{%0,%1,%2,%3}, {%4,%5,%6,%7}, {%8,%9}, {%0,%1,%2,%3};\n"
        : "+f"(c[0]), "+f"(c[1]), "+f"(c[2]), "+f"(c[3])
        : "r"(a[0]), "r"(a[1]), "r"(a[2]), "r"(a[3]), "r"(b[0]), "r"(b[1]));
}

__global__ void k_logits(const float* __restrict__ b_fc, float* __restrict__ out)
{
    const int bn = blockIdx.x * 128;
    const int bm = blockIdx.y * 64;
    const int tid = threadIdx.x;
    const int wid = tid >> 5, lane = tid & 31;
    const int warp_m = wid >> 2, warp_n = wid & 3;
    const int g = lane >> 2, tg = lane & 3;

    __shared__ __nv_bfloat16 As[64][40];
    __shared__ __nv_bfloat16 Bs[128][40];
    __shared__ float bsm[128];
    __shared__ float ses[64];
    if (tid < 128) bsm[tid] = b_fc[bn + tid];
    if (tid < 64)  ses[tid] = 0.f;

    float acc[2][4][4];
#pragma unroll
    for (int i = 0; i < 2; i++)
#pragma unroll
        for (int j = 0; j < 4; j++)
#pragma unroll
            for (int r = 0; r < 4; r++) acc[i][j][r] = 0.f;

    for (int k0 = 0; k0 < HSZ; k0 += 32) {
        {
            int r = tid >> 2, cg = (tid & 3) << 3;
            uint4 v = *(const uint4*)(g_YSb + (size_t)(bm + r) * HSZ + k0 + cg);
            *(uint4*)&As[r][cg] = v;
        }
        {
            int r = tid >> 1, h = tid & 1;
            const uint4* src = (const uint4*)(g_WFCb + (size_t)(bn + r) * HSZ + k0 + h*16);
            *(uint4*)&Bs[r][h*16]     = src[0];
            *(uint4*)&Bs[r][h*16 + 8] = src[1];
        }
        __syncthreads();
#pragma unroll
        for (int kk = 0; kk < 32; kk += 16) {
            uint32_t af[2][4], bfr[4][2];
#pragma unroll
            for (int im = 0; im < 2; im++) {
                int r0 = warp_m*32 + im*16;
                af[im][0] = *(const uint32_t*)&As[r0 + g    ][kk + tg*2    ];
                af[im][1] = *(const uint32_t*)&As[r0 + g + 8][kk + tg*2    ];
                af[im][2] = *(const uint32_t*)&As[r0 + g    ][kk + tg*2 + 8];
                af[im][3] = *(const uint32_t*)&As[r0 + g + 8][kk + tg*2 + 8];
            }
#pragma unroll
            for (int in_ = 0; in_ < 4; in_++) {
                int c0 = warp_n*32 + in_*8;
                bfr[in_][0] = *(const uint32_t*)&Bs[c0 + g][kk + tg*2    ];
                bfr[in_][1] = *(const uint32_t*)&Bs[c0 + g][kk + tg*2 + 8];
            }
#pragma unroll
            for (int im = 0; im < 2; im++)
#pragma unroll
                for (int in_ = 0; in_ < 4; in_++)
                    mma16816(acc[im][in_], af[im], bfr[in_]);
        }
        __syncthreads();
    }

#pragma unroll
    for (int im = 0; im < 2; im++) {
#pragma unroll
        for (int half = 0; half < 2; half++) {
            const int row_l = warp_m*32 + im*16 + g + half*8;
            const int row = bm + row_l;
            float s = 0.f;
#pragma unroll
            for (int in_ = 0; in_ < 4; in_++) {
                const int col_l = warp_n*32 + in_*8 + tg*2;
                float v0 = acc[im][in_][half*2 + 0] + bsm[col_l];
                float v1 = acc[im][in_][half*2 + 1] + bsm[col_l + 1];
                float2 st; st.x = v0; st.y = v1;
                *(float2*)(out + (size_t)row * VSZ + bn + col_l) = st;
                s += __expf(v0) + __expf(v1);
            }
            atomicAdd(&ses[row_l], s);
        }
    }
    __syncthreads();
    if (tid < 64) atomicAdd(&g_SUMEXP[bm + tid], ses[tid]);
}

// ---------------- fixup: out -= log(sumexp(row)) ---------------------------
__global__ void k_fix(float* __restrict__ out)
{
    const size_t i = (size_t)blockIdx.x * 256 + threadIdx.x;  // over float4s
    const int row = (int)(i / (VSZ / 4));
    const float l = logf(g_SUMEXP[row]);
    float4 v = ((const float4*)out)[i];
    v.x -= l; v.y -= l; v.z -= l; v.w -= l;
    ((float4*)out)[i] = v;
}

// ---------------- launch ---------------------------------------------------
extern "C" void kernel_launch(void* const* d_in, const int* in_sizes, int n_in,
                              void* d_out, int out_size)
{
    const float* ctx     = (const float*)d_in[0];
    const int*   targets = (const int*)  d_in[1];
    const float* emb     = (const float*)d_in[2];
    const float* W_init  = (const float*)d_in[3];
    const float* b_init  = (const float*)d_in[4];
    const float* Wi0     = (const float*)d_in[5];
    const float* Wh0     = (const float*)d_in[6];
    const float* bi0     = (const float*)d_in[7];
    const float* bh0     = (const float*)d_in[8];
    const float* Wi1     = (const float*)d_in[9];
    const float* Wh1     = (const float*)d_in[10];
    const float* bi1     = (const float*)d_in[11];
    const float* bh1     = (const float*)d_in[12];
    const float* W_fc    = (const float*)d_in[13];
    const float* b_fc    = (const float*)d_in[14];
    float* out = (float*)d_out;

    static int smem_set = 0;
    const int scan_smem = (72 * WPAD + 2 * 64 * APAD) * 4;   // 216192 B
    if (!smem_set) {
        cudaFuncSetAttribute(k_scan, cudaFuncAttributeMaxDynamicSharedMemorySize, scan_smem);
        smem_set = 1;
    }

    k_h0<<<128, 128>>>(ctx, W_init, b_init);
    k_cvt_wfc<<<(VSZ * HSZ / 4) / 256, 256>>>(W_fc);
    k_gi0<<<dim3(24, TSZ), 256>>>(emb, targets, Wi0, bi0);

    k_scan<<<NC, 128, scan_smem>>>(Wh0, bh0, Wi1, Wh1, bi1, bh1);

    k_logits<<<dim3(VSZ / 128, MROWS / 64), 256>>>(b_fc, out);
    k_fix<<<((size_t)MROWS * VSZ / 4) / 256, 256>>>(out);
}

// round 5
// speedup vs baseline: 4.2311x; 1.2352x over previous
#include <cuda_runtime.h>
#include <cuda_bf16.h>
#include <cstdint>

// Shapes
#define VSZ   32000
#define ESZ   512
#define HSZ   512
#define BSZ   64
#define TSZ   65          // sequence steps
#define G3    1536        // 3*H
#define MROWS (BSZ*TSZ)   // 4160 output rows

#define NC    64          // persistent scan CTAs (1 wave, co-resident)
#define WB    520         // bf16 row stride (512 + 8): stride%32words==4 -> conflict-free

// ---------------- device scratch (static allocations only) ----------------
__device__ float          g_HA[2 * BSZ * HSZ];
__device__ float          g_HB[2 * BSZ * HSZ];
__device__ float          g_GI0[TSZ * BSZ * G3];        // 25.6 MB
__device__ __nv_bfloat16  g_WFCb[(size_t)VSZ * HSZ];    // 32.8 MB
__device__ __nv_bfloat16  g_YSb[(size_t)MROWS * HSZ];   // 4.3 MB
__device__ float          g_SUMEXP[MROWS];
__device__ unsigned       g_cnt;

__device__ __forceinline__ float sigf(float x) { return 1.f / (1.f + __expf(-x)); }

// bf16 mma m16n8k16, fp32 accumulate
__device__ __forceinline__ void mma16816(float* c, const uint32_t* a, uint32_t b0, uint32_t b1)
{
    asm volatile(
        "mma.sync.aligned.m16n8k16.row.col.f32.bf16.bf16.f32 "
        "{%0,%1,%2,%3}, {%4,%5,%6,%7}, {%8,%9}, {%0,%1,%2,%3};\n"
        : "+f"(c[0]), "+f"(c[1]), "+f"(c[2]), "+f"(c[3])
        : "r"(a[0]), "r"(a[1]), "r"(a[2]), "r"(a[3]), "r"(b0), "r"(b1));
}

// grid-wide barrier: RED arrive + LOAD-based (non-RMW) polling
__device__ __forceinline__ void gbar(unsigned target) {
    __syncthreads();
    if (threadIdx.x == 0) {
        unsigned* p = &g_cnt;
        asm volatile("red.release.gpu.global.add.u32 [%0], 1;" :: "l"(p) : "memory");
        unsigned v;
        do {
            asm volatile("ld.acquire.gpu.global.u32 %0, [%1];" : "=r"(v) : "l"(p) : "memory");
        } while (v < target);
    }
    __syncthreads();
}

// ---------------- h0 = tanh(ctx @ W_init^T + b_init); zero SUMEXP,cnt -----
__global__ void k_h0(const float* __restrict__ ctx,
                     const float* __restrict__ W_init,
                     const float* __restrict__ b_init)
{
    const int lb = blockIdx.x;
    const int l = lb >> 6, b = lb & 63;
    const int tid = threadIdx.x;
    __shared__ float cs[HSZ];
    ((float4*)cs)[tid] = ((const float4*)(ctx + (size_t)lb * HSZ))[tid];

    const int gid = blockIdx.x * 128 + tid;
    if (gid < MROWS) g_SUMEXP[gid] = 0.f;
    if (gid == 0) g_cnt = 0;
    __syncthreads();

    float* hout = (l == 0) ? g_HA : g_HB;   // buffer index 0
#pragma unroll
    for (int jj = 0; jj < 4; jj++) {
        const int j = tid * 4 + jj;
        const float* wr = W_init + (size_t)j * HSZ;
        float acc = 0.f;
        for (int k = 0; k < HSZ; k += 4) {
            float4 w = *(const float4*)(wr + k);
            acc += w.x * cs[k] + w.y * cs[k+1] + w.z * cs[k+2] + w.w * cs[k+3];
        }
        hout[b * HSZ + j] = tanhf(acc + b_init[j]);
    }
}

// ---------------- W_fc fp32 -> bf16 ---------------------------------------
__global__ void k_cvt_wfc(const float* __restrict__ wfc)
{
    const size_t i = (size_t)blockIdx.x * 256 + threadIdx.x;
    float4 v = ((const float4*)wfc)[i];
    __nv_bfloat162 lo = __floats2bfloat162_rn(v.x, v.y);
    __nv_bfloat162 hi = __floats2bfloat162_rn(v.z, v.w);
    uint2 o; o.x = *(uint32_t*)&lo; o.y = *(uint32_t*)&hi;
    ((uint2*)g_WFCb)[i] = o;
}

// ---------------- GI0[t,b,:] = emb[tok(t,b)] @ Wi0^T + bi0 ----------------
__global__ void k_gi0(const float* __restrict__ emb,
                      const int*   __restrict__ targets,
                      const float* __restrict__ Wi0,
                      const float* __restrict__ bi0)
{
    const int bn = blockIdx.x * 64;
    const int t  = blockIdx.y;
    const int tid = threadIdx.x;
    const int tx = tid & 15, ty = tid >> 4;
    __shared__ float As[64][33];
    __shared__ float Bs[64][33];
    __shared__ int   toks[64];
    if (tid < 64) toks[tid] = (t == 0) ? 1 : targets[tid * TSZ + t - 1];
    __syncthreads();

    float acc[4][4];
#pragma unroll
    for (int i = 0; i < 4; i++)
#pragma unroll
        for (int j = 0; j < 4; j++) acc[i][j] = 0.f;

    for (int k0 = 0; k0 < ESZ; k0 += 32) {
        for (int i = tid; i < 512; i += 256) {
            int r = i >> 3, cg = (i & 7) << 2;
            float4 v = *(const float4*)(emb + (size_t)toks[r] * ESZ + k0 + cg);
            As[r][cg] = v.x; As[r][cg+1] = v.y; As[r][cg+2] = v.z; As[r][cg+3] = v.w;
        }
        for (int i = tid; i < 512; i += 256) {
            int r = i >> 3, cg = (i & 7) << 2;
            float4 v = *(const float4*)(Wi0 + (size_t)(bn + r) * ESZ + k0 + cg);
            Bs[r][cg] = v.x; Bs[r][cg+1] = v.y; Bs[r][cg+2] = v.z; Bs[r][cg+3] = v.w;
        }
        __syncthreads();
#pragma unroll
        for (int k = 0; k < 32; k++) {
            float a[4], bb[4];
#pragma unroll
            for (int i = 0; i < 4; i++) a[i] = As[ty*4+i][k];
#pragma unroll
            for (int j = 0; j < 4; j++) bb[j] = Bs[tx*4+j][k];
#pragma unroll
            for (int i = 0; i < 4; i++)
#pragma unroll
                for (int j = 0; j < 4; j++) acc[i][j] += a[i] * bb[j];
        }
        __syncthreads();
    }
#pragma unroll
    for (int i = 0; i < 4; i++) {
        const int b = ty*4 + i;
#pragma unroll
        for (int j = 0; j < 4; j++) {
            const int n = bn + tx*4 + j;
            g_GI0[((size_t)t * BSZ + b) * G3 + n] = acc[i][j] + bi0[n];
        }
    }
}

// coalesced fp32->bf16 staging of full 64x512 rows (NR rows per warp)
template<int NR>
__device__ __forceinline__ void stage_bf16(const float* __restrict__ src,
                                           __nv_bfloat16* __restrict__ dst,
                                           int lane, int row0)
{
#pragma unroll
    for (int i = 0; i < NR; i++) {
        const int row = row0 + i;
        const float4* s = (const float4*)(src + (size_t)row * HSZ);
        __nv_bfloat16* d = dst + (size_t)row * WB;
#pragma unroll
        for (int c = 0; c < 4; c++) {
            float4 v = __ldcg(s + c * 32 + lane);
            __nv_bfloat162 p0 = __floats2bfloat162_rn(v.x, v.y);
            __nv_bfloat162 p1 = __floats2bfloat162_rn(v.z, v.w);
            uint2 o; o.x = *(uint32_t*)&p0; o.y = *(uint32_t*)&p1;
            *(uint2*)(d + c * 128 + lane * 4) = o;
        }
    }
}

// ---------------- persistent fused GRU scan (both cells, all 65 steps) ----
// 64 CTAs x 128 threads; CTA owns 8 j-columns x 3 gates. bf16 mma, fp32 state.
__global__ void __launch_bounds__(128, 1) k_scan(
    const float* __restrict__ Wh0, const float* __restrict__ bh0,
    const float* __restrict__ Wi1, const float* __restrict__ Wh1,
    const float* __restrict__ bi1, const float* __restrict__ bh1)
{
    extern __shared__ __nv_bfloat16 smb[];
    __nv_bfloat16* Wh0s = smb;                 // [24][WB]
    __nv_bfloat16* Wi1s = smb + 24 * WB;
    __nv_bfloat16* Wh1s = smb + 48 * WB;
    __nv_bfloat16* Axs  = smb + 72 * WB;       // [64][WB]
    __nv_bfloat16* Ahs  = Axs + 64 * WB;

    const int tid  = threadIdx.x;
    const int wid  = tid >> 5, lane = tid & 31;
    const int g    = lane >> 2, tg = lane & 3;
    const int m0   = wid * 16;
    const int jb   = blockIdx.x * 8;

    // ---- load weight slices once (bf16) ----
    for (int r = 0; r < 24; r++) {
        const int gate = r >> 3, jj = r & 7;
        const size_t grow = (size_t)(gate * HSZ + jb + jj) * HSZ + tid * 4;
        float4 v0 = *(const float4*)(Wh0 + grow);
        float4 v1 = *(const float4*)(Wi1 + grow);
        float4 v2 = *(const float4*)(Wh1 + grow);
        const int o = r * WB + tid * 4;
        {
            __nv_bfloat162 p0 = __floats2bfloat162_rn(v0.x, v0.y);
            __nv_bfloat162 p1 = __floats2bfloat162_rn(v0.z, v0.w);
            uint2 u; u.x = *(uint32_t*)&p0; u.y = *(uint32_t*)&p1;
            *(uint2*)(Wh0s + o) = u;
        }
        {
            __nv_bfloat162 p0 = __floats2bfloat162_rn(v1.x, v1.y);
            __nv_bfloat162 p1 = __floats2bfloat162_rn(v1.z, v1.w);
            uint2 u; u.x = *(uint32_t*)&p0; u.y = *(uint32_t*)&p1;
            *(uint2*)(Wi1s + o) = u;
        }
        {
            __nv_bfloat162 p0 = __floats2bfloat162_rn(v2.x, v2.y);
            __nv_bfloat162 p1 = __floats2bfloat162_rn(v2.z, v2.w);
            uint2 u; u.x = *(uint32_t*)&p0; u.y = *(uint32_t*)&p1;
            *(uint2*)(Wh1s + o) = u;
        }
    }
    __syncthreads();

    // ---- preload biases for this thread's 2 j columns ----
    float bg0[3][2], bgi1[3][2], bgh1[3][2];
#pragma unroll
    for (int gi = 0; gi < 3; gi++)
#pragma unroll
        for (int cc = 0; cc < 2; cc++) {
            const int j = gi * HSZ + jb + 2 * tg + cc;
            bg0[gi][cc]  = bh0[j];
            bgi1[gi][cc] = bi1[j];
            bgh1[gi][cc] = bh1[j];
        }

    // ================= cell0 body =================
    auto do_cell0 = [&](int t) {
        const float* hAin  = g_HA + (t & 1) * (BSZ * HSZ);
        float*       hAout = g_HA + ((t & 1) ^ 1) * (BSZ * HSZ);

        stage_bf16<16>(hAin, Axs, lane, wid * 16);
        __syncthreads();

        float acc0[3][4];
#pragma unroll
        for (int gi = 0; gi < 3; gi++)
#pragma unroll
            for (int r = 0; r < 4; r++) acc0[gi][r] = 0.f;

#pragma unroll
        for (int ks = 0; ks < 32; ks++) {
            const int k = ks * 16;
            const __nv_bfloat16* ar0 = Axs + (m0 + g) * WB + k + tg * 2;
            const __nv_bfloat16* ar1 = Axs + (m0 + g + 8) * WB + k + tg * 2;
            uint32_t a[4];
            a[0] = *(const uint32_t*)ar0;
            a[1] = *(const uint32_t*)ar1;
            a[2] = *(const uint32_t*)(ar0 + 8);
            a[3] = *(const uint32_t*)(ar1 + 8);
#pragma unroll
            for (int gi = 0; gi < 3; gi++) {
                const __nv_bfloat16* br = Wh0s + (gi * 8 + g) * WB + k + tg * 2;
                mma16816(acc0[gi], a, *(const uint32_t*)br, *(const uint32_t*)(br + 8));
            }
        }
        __syncthreads();   // all warps done reading Axs before next stage

#pragma unroll
        for (int hf = 0; hf < 2; hf++) {
            const int b = m0 + g + 8 * hf;
            const float* gi0p = g_GI0 + ((size_t)t * BSZ + b) * G3;
#pragma unroll
            for (int cc = 0; cc < 2; cc++) {
                const int j = jb + 2 * tg + cc;
                const float r = sigf(__ldg(gi0p + j)          + acc0[0][hf*2+cc] + bg0[0][cc]);
                const float z = sigf(__ldg(gi0p + HSZ + j)    + acc0[1][hf*2+cc] + bg0[1][cc]);
                const float n = tanhf(__ldg(gi0p + 2*HSZ + j) + r * (acc0[2][hf*2+cc] + bg0[2][cc]));
                const float hprev = __ldcg(hAin + (size_t)b * HSZ + j);
                hAout[(size_t)b * HSZ + j] = (1.f - z) * n + z * hprev;
            }
        }
    };

    // ================= cell1 body =================
    auto do_cell1 = [&](int t) {
        const float* hx   = g_HA + ((t & 1) ^ 1) * (BSZ * HSZ);  // hAout(t)
        const float* hBin = g_HB + (t & 1) * (BSZ * HSZ);
        float*      hBout = g_HB + ((t & 1) ^ 1) * (BSZ * HSZ);

        if (wid < 2) stage_bf16<32>(hx,   Axs, lane, wid * 32);
        else         stage_bf16<32>(hBin, Ahs, lane, (wid - 2) * 32);
        __syncthreads();

        float accx[3][4], acch[3][4];
#pragma unroll
        for (int gi = 0; gi < 3; gi++)
#pragma unroll
            for (int r = 0; r < 4; r++) { accx[gi][r] = 0.f; acch[gi][r] = 0.f; }

#pragma unroll
        for (int ks = 0; ks < 32; ks++) {
            const int k = ks * 16;
            const __nv_bfloat16* ax0 = Axs + (m0 + g) * WB + k + tg * 2;
            const __nv_bfloat16* ax1 = Axs + (m0 + g + 8) * WB + k + tg * 2;
            const __nv_bfloat16* ah0 = Ahs + (m0 + g) * WB + k + tg * 2;
            const __nv_bfloat16* ah1 = Ahs + (m0 + g + 8) * WB + k + tg * 2;
            uint32_t ax[4], ah[4];
            ax[0] = *(const uint32_t*)ax0;       ah[0] = *(const uint32_t*)ah0;
            ax[1] = *(const uint32_t*)ax1;       ah[1] = *(const uint32_t*)ah1;
            ax[2] = *(const uint32_t*)(ax0 + 8); ah[2] = *(const uint32_t*)(ah0 + 8);
            ax[3] = *(const uint32_t*)(ax1 + 8); ah[3] = *(const uint32_t*)(ah1 + 8);
#pragma unroll
            for (int gi = 0; gi < 3; gi++) {
                const __nv_bfloat16* bi_ = Wi1s + (gi * 8 + g) * WB + k + tg * 2;
                const __nv_bfloat16* bh_ = Wh1s + (gi * 8 + g) * WB + k + tg * 2;
                mma16816(accx[gi], ax, *(const uint32_t*)bi_, *(const uint32_t*)(bi_ + 8));
                mma16816(acch[gi], ah, *(const uint32_t*)bh_, *(const uint32_t*)(bh_ + 8));
            }
        }
        __syncthreads();

#pragma unroll
        for (int hf = 0; hf < 2; hf++) {
            const int b = m0 + g + 8 * hf;
#pragma unroll
            for (int cc = 0; cc < 2; cc++) {
                const int j = jb + 2 * tg + cc;
                const float r = sigf(accx[0][hf*2+cc] + bgi1[0][cc] + acch[0][hf*2+cc] + bgh1[0][cc]);
                const float z = sigf(accx[1][hf*2+cc] + bgi1[1][cc] + acch[1][hf*2+cc] + bgh1[1][cc]);
                const float n = tanhf(accx[2][hf*2+cc] + bgi1[2][cc]
                                      + r * (acch[2][hf*2+cc] + bgh1[2][cc]));
                const float hprev = __ldcg(hBin + (size_t)b * HSZ + j);
                const float v = (1.f - z) * n + z * hprev;
                hBout[(size_t)b * HSZ + j] = v;
                g_YSb[((size_t)b * TSZ + t) * HSZ + j] = __float2bfloat16(v);
            }
        }
    };

    // ===== phase-grouped schedule: ONE barrier per step =====
    do_cell0(0);
    gbar(NC);
    for (int t = 0; t < TSZ; t++) {
        do_cell1(t);
        if (t < TSZ - 1) {
            do_cell0(t + 1);
            gbar((unsigned)(t + 2) * NC);
        }
    }
}

// ---------------- logits GEMM (bf16 mma) + fused sum-of-exp ---------------
// tile 128(m) x 128(n), 256 threads (2x4 warps, each warp 64m x 32n)
__global__ void k_logits(const float* __restrict__ b_fc, float* __restrict__ out)
{
    const int bn = blockIdx.x * 128;
    const int bm = blockIdx.y * 128;
    const int tid = threadIdx.x;
    const int wid = tid >> 5, lane = tid & 31;
    const int warp_m = wid >> 2, warp_n = wid & 3;
    const int g = lane >> 2, tg = lane & 3;

    __shared__ __nv_bfloat16 As[128][40];
    __shared__ __nv_bfloat16 Bs[128][40];
    __shared__ float bsm[128];
    __shared__ float ses[128];
    if (tid < 128) { bsm[tid] = b_fc[bn + tid]; ses[tid] = 0.f; }

    float acc[4][4][4];
#pragma unroll
    for (int i = 0; i < 4; i++)
#pragma unroll
        for (int j = 0; j < 4; j++)
#pragma unroll
            for (int r = 0; r < 4; r++) acc[i][j][r] = 0.f;

    for (int k0 = 0; k0 < HSZ; k0 += 32) {
        for (int i = tid; i < 512; i += 256) {
            int r = i >> 2, q = i & 3;
            int row = bm + r; if (row >= MROWS) row = MROWS - 1;
            *(uint4*)&As[r][q * 8] = *(const uint4*)(g_YSb + (size_t)row * HSZ + k0 + q * 8);
        }
        for (int i = tid; i < 512; i += 256) {
            int r = i >> 2, q = i & 3;
            *(uint4*)&Bs[r][q * 8] = *(const uint4*)(g_WFCb + (size_t)(bn + r) * HSZ + k0 + q * 8);
        }
        __syncthreads();
#pragma unroll
        for (int kk = 0; kk < 32; kk += 16) {
            uint32_t af[4][4], bfr[4][2];
#pragma unroll
            for (int im = 0; im < 4; im++) {
                int r0 = warp_m * 64 + im * 16;
                af[im][0] = *(const uint32_t*)&As[r0 + g    ][kk + tg*2    ];
                af[im][1] = *(const uint32_t*)&As[r0 + g + 8][kk + tg*2    ];
                af[im][2] = *(const uint32_t*)&As[r0 + g    ][kk + tg*2 + 8];
                af[im][3] = *(const uint32_t*)&As[r0 + g + 8][kk + tg*2 + 8];
            }
#pragma unroll
            for (int in_ = 0; in_ < 4; in_++) {
                int c0 = warp_n * 32 + in_ * 8;
                bfr[in_][0] = *(const uint32_t*)&Bs[c0 + g][kk + tg*2    ];
                bfr[in_][1] = *(const uint32_t*)&Bs[c0 + g][kk + tg*2 + 8];
            }
#pragma unroll
            for (int im = 0; im < 4; im++)
#pragma unroll
                for (int in_ = 0; in_ < 4; in_++)
                    mma16816(acc[im][in_], af[im], bfr[in_][0], bfr[in_][1]);
        }
        __syncthreads();
    }

#pragma unroll
    for (int im = 0; im < 4; im++) {
#pragma unroll
        for (int half = 0; half < 2; half++) {
            const int row_l = warp_m * 64 + im * 16 + g + half * 8;
            const int row = bm + row_l;
            if (row >= MROWS) continue;
            float s = 0.f;
#pragma unroll
            for (int in_ = 0; in_ < 4; in_++) {
                const int col_l = warp_n * 32 + in_ * 8 + tg * 2;
                float v0 = acc[im][in_][half*2 + 0] + bsm[col_l];
                float v1 = acc[im][in_][half*2 + 1] + bsm[col_l + 1];
                float2 st; st.x = v0; st.y = v1;
                *(float2*)(out + (size_t)row * VSZ + bn + col_l) = st;
                s += __expf(v0) + __expf(v1);
            }
            atomicAdd(&ses[row_l], s);
        }
    }
    __syncthreads();
    if (tid < 128 && bm + tid < MROWS) atomicAdd(&g_SUMEXP[bm + tid], ses[tid]);
}

// ---------------- fixup: out -= log(sumexp(row)) ---------------------------
__global__ void k_fix(float* __restrict__ out)
{
    const size_t i = (size_t)blockIdx.x * 256 + threadIdx.x;  // over float4s
    const int row = (int)(i / (VSZ / 4));
    const float l = logf(g_SUMEXP[row]);
    float4 v = ((const float4*)out)[i];
    v.x -= l; v.y -= l; v.z -= l; v.w -= l;
    ((float4*)out)[i] = v;
}

// ---------------- launch ---------------------------------------------------
extern "C" void kernel_launch(void* const* d_in, const int* in_sizes, int n_in,
                              void* d_out, int out_size)
{
    const float* ctx     = (const float*)d_in[0];
    const int*   targets = (const int*)  d_in[1];
    const float* emb     = (const float*)d_in[2];
    const float* W_init  = (const float*)d_in[3];
    const float* b_init  = (const float*)d_in[4];
    const float* Wi0     = (const float*)d_in[5];
    const float* Wh0     = (const float*)d_in[6];
    const float* bi0     = (const float*)d_in[7];
    const float* bh0     = (const float*)d_in[8];
    const float* Wi1     = (const float*)d_in[9];
    const float* Wh1     = (const float*)d_in[10];
    const float* bi1     = (const float*)d_in[11];
    const float* bh1     = (const float*)d_in[12];
    const float* W_fc    = (const float*)d_in[13];
    const float* b_fc    = (const float*)d_in[14];
    float* out = (float*)d_out;

    static int smem_set = 0;
    const int scan_smem = (72 * WB + 2 * 64 * WB) * 2;   // 208,000 B
    if (!smem_set) {
        cudaFuncSetAttribute(k_scan, cudaFuncAttributeMaxDynamicSharedMemorySize, scan_smem);
        smem_set = 1;
    }

    k_h0<<<128, 128>>>(ctx, W_init, b_init);
    k_cvt_wfc<<<(VSZ * HSZ / 4) / 256, 256>>>(W_fc);
    k_gi0<<<dim3(24, TSZ), 256>>>(emb, targets, Wi0, bi0);

    k_scan<<<NC, 128, scan_smem>>>(Wh0, bh0, Wi1, Wh1, bi1, bh1);

    k_logits<<<dim3(VSZ / 128, (MROWS + 127) / 128), 256>>>(b_fc, out);
    k_fix<<<((size_t)MROWS * VSZ / 4) / 256, 256>>>(out);
}